// round 2
// baseline (speedup 1.0000x reference)
#include <cuda_runtime.h>
#include <math_constants.h>

#define BATCH 8192
#define DIM   512
#define T_INV 14.2857142857142857f  // 1/0.07

#define BM 64
#define BN 64
#define BK 32
#define PAD 68   // row pad (floats): keeps float4 alignment (68*4=272=16*17) and banks spread

// scratch (static device memory: allocation-free per harness rules)
__device__ float g_f[BATCH * DIM];     // normalized features
__device__ int   g_idx[BATCH];         // canonical int32 indices
__device__ float g_S[BATCH];           // sum of sim over positives
__device__ float g_P[BATCH];           // sum exp(sim/T) over positives
__device__ float g_rm[BATCH];          // max positive sim
__device__ float g_n[BATCH];           // positive count
__device__ float g_H[BATCH];           // sum exp(topk/T)
__device__ float g_tmax[BATCH];        // top-1 off-diagonal sim

// ---------------------------------------------------------------------------
// Kernel 0: dtype-agnostic index canonicalization.
// Reads only the first 8192 int32 words (32 KB) — in-bounds whether the
// indices buffer is int32 (8192*4B) or int64 (8192*8B). For int64 (values in
// [0,512), little-endian) every odd word is 0; for int32 the odd words are
// random indices and their OR is nonzero w.p. 1 - (1/512)^4096.
// ---------------------------------------------------------------------------
__global__ void prep_idx_kernel(const int* __restrict__ raw) {
    __shared__ int sh[256];
    int tid = threadIdx.x;
    int acc = 0;
    for (int i = tid; i < BATCH / 2; i += 256) acc |= raw[2 * i + 1];
    sh[tid] = acc;
    __syncthreads();
    for (int s = 128; s; s >>= 1) {
        if (tid < s) sh[tid] |= sh[tid + s];
        __syncthreads();
    }
    bool is64 = (sh[0] == 0);
    for (int i = tid; i < BATCH; i += 256)
        g_idx[i] = is64 ? raw[2 * i] : raw[i];
}

// ---------------------------------------------------------------------------
// Kernel 1: L2 normalize rows (eps clamp 1e-12, matching torch F.normalize)
// ---------------------------------------------------------------------------
__global__ void normalize_kernel(const float* __restrict__ x) {
    int row = blockIdx.x;
    int t = threadIdx.x;  // 128 threads, one float4 each (512 floats/row)
    const float4* xr = (const float4*)(x + row * DIM);
    float4 v = xr[t];
    float ss = v.x * v.x + v.y * v.y + v.z * v.z + v.w * v.w;
    #pragma unroll
    for (int o = 16; o; o >>= 1) ss += __shfl_xor_sync(0xffffffffu, ss, o);
    __shared__ float ws[4];
    if ((t & 31) == 0) ws[t >> 5] = ss;
    __syncthreads();
    float tot = ws[0] + ws[1] + ws[2] + ws[3];
    float inv = 1.0f / fmaxf(sqrtf(tot), 1e-12f);
    v.x *= inv; v.y *= inv; v.z *= inv; v.w *= inv;
    ((float4*)(g_f + row * DIM))[t] = v;
}

// ---------------------------------------------------------------------------
// Kernel 2: fused sim GEMM + per-row streaming reductions
//   grid = 128 blocks (64 rows each), 256 threads.
//   A tile [512][PAD] resident (transposed, loaded once); B streamed in 32-K
//   chunks; 4x4 register microtile per thread; C tile staged in SMEM; threads
//   0..63 (one per row) scan each 64-col tile updating top-5 + positive stats.
// ---------------------------------------------------------------------------
__global__ __launch_bounds__(256, 1)
void sim_kernel() {
    extern __shared__ float smem[];
    float* As   = smem;                      // [512][PAD]
    float* Bs   = As + DIM * PAD;            // [BK][PAD]
    float* Cs   = Bs + BK * PAD;             // [BM][PAD]
    int*   idxB = (int*)(Cs + BM * PAD);     // [BN]

    const int tid  = threadIdx.x;
    const int row0 = blockIdx.x * BM;
    const int tx = tid & 15, ty = tid >> 4;

    // Load A tile transposed: As[k][r]  (coalesced global reads along k)
    for (int i = tid; i < BM * DIM; i += 256) {
        int r = i >> 9;          // i / 512
        int k = i & (DIM - 1);   // i % 512
        As[k * PAD + r] = g_f[(row0 + r) * DIM + k];
    }

    // per-row scan state (live only in threads 0..63)
    float S = 0.f, P = 0.f, rm = -CUDART_INF_F, n = 0.f;
    float t0 = -CUDART_INF_F, t1 = -CUDART_INF_F, t2 = -CUDART_INF_F,
          t3 = -CUDART_INF_F, t4 = -CUDART_INF_F;
    const int myrow = row0 + tid;
    const int myidx = (tid < BM) ? g_idx[myrow] : 0;

    __syncthreads();

    for (int c0 = 0; c0 < BATCH; c0 += BN) {
        if (tid < BN) idxB[tid] = g_idx[c0 + tid];

        float acc[4][4] = {};
        for (int k0 = 0; k0 < DIM; k0 += BK) {
            __syncthreads();  // Bs consumed by previous chunk / idxB vs. scan
            // load Bs[kk][col]: 64 cols x 32 k, float4 granular, conflict-free writes
            for (int i = tid; i < (BN * BK) / 4; i += 256) {
                int col = i >> 3;
                int kq  = i & 7;
                float4 v = *(const float4*)(g_f + (c0 + col) * DIM + k0 + kq * 4);
                int kk = kq * 4;
                Bs[(kk + 0) * PAD + col] = v.x;
                Bs[(kk + 1) * PAD + col] = v.y;
                Bs[(kk + 2) * PAD + col] = v.z;
                Bs[(kk + 3) * PAD + col] = v.w;
            }
            __syncthreads();
            #pragma unroll 8
            for (int kk = 0; kk < BK; kk++) {
                float4 a = *(const float4*)(As + (k0 + kk) * PAD + (ty << 2));
                float4 b = *(const float4*)(Bs + kk * PAD + (tx << 2));
                acc[0][0] = fmaf(a.x, b.x, acc[0][0]);
                acc[0][1] = fmaf(a.x, b.y, acc[0][1]);
                acc[0][2] = fmaf(a.x, b.z, acc[0][2]);
                acc[0][3] = fmaf(a.x, b.w, acc[0][3]);
                acc[1][0] = fmaf(a.y, b.x, acc[1][0]);
                acc[1][1] = fmaf(a.y, b.y, acc[1][1]);
                acc[1][2] = fmaf(a.y, b.z, acc[1][2]);
                acc[1][3] = fmaf(a.y, b.w, acc[1][3]);
                acc[2][0] = fmaf(a.z, b.x, acc[2][0]);
                acc[2][1] = fmaf(a.z, b.y, acc[2][1]);
                acc[2][2] = fmaf(a.z, b.z, acc[2][2]);
                acc[2][3] = fmaf(a.z, b.w, acc[2][3]);
                acc[3][0] = fmaf(a.w, b.x, acc[3][0]);
                acc[3][1] = fmaf(a.w, b.y, acc[3][1]);
                acc[3][2] = fmaf(a.w, b.z, acc[3][2]);
                acc[3][3] = fmaf(a.w, b.w, acc[3][3]);
            }
        }

        // stage C tile to SMEM
        #pragma unroll
        for (int i = 0; i < 4; i++) {
            *(float4*)(Cs + ((ty << 2) + i) * PAD + (tx << 2)) =
                make_float4(acc[i][0], acc[i][1], acc[i][2], acc[i][3]);
        }
        __syncthreads();

        // per-row scan: threads 0..63, one row each
        if (tid < BM) {
            const float* crow = Cs + tid * PAD;
            #pragma unroll 4
            for (int cc = 0; cc < BN; cc++) {
                int gcol = c0 + cc;
                if (gcol == myrow) continue;  // exclude diagonal everywhere
                float v = crow[cc];
                if (v > t4) {  // top-5 insertion (sorted descending)
                    float w = v, tmp;
                    if (w > t0) { tmp = t0; t0 = w; w = tmp; }
                    if (w > t1) { tmp = t1; t1 = w; w = tmp; }
                    if (w > t2) { tmp = t2; t2 = w; w = tmp; }
                    if (w > t3) { tmp = t3; t3 = w; w = tmp; }
                    t4 = w;
                }
                if (idxB[cc] == myidx) {
                    n += 1.0f;
                    S += v;
                    rm = fmaxf(rm, v);
                    P += __expf(v * T_INV);
                }
            }
        }
        __syncthreads();  // scan done before idxB/Bs overwrite next iteration
    }

    if (tid < BM) {
        int r = row0 + tid;
        g_S[r] = S; g_P[r] = P; g_rm[r] = rm; g_n[r] = n;
        g_tmax[r] = t0;
        g_H[r] = __expf(t0 * T_INV) + __expf(t1 * T_INV) + __expf(t2 * T_INV) +
                 __expf(t3 * T_INV) + __expf(t4 * T_INV);
    }
}

// ---------------------------------------------------------------------------
// Kernel 3: global-max reduction + per-row loss + mean
// ---------------------------------------------------------------------------
__global__ void finalize_kernel(float* __restrict__ out) {
    __shared__ float sh[256];
    int tid = threadIdx.x;

    float m = -CUDART_INF_F;
    for (int r = tid; r < BATCH; r += 256) m = fmaxf(m, g_tmax[r]);
    sh[tid] = m;
    __syncthreads();
    for (int s = 128; s; s >>= 1) {
        if (tid < s) sh[tid] = fmaxf(sh[tid], sh[tid + s]);
        __syncthreads();
    }
    float G = sh[0] * T_INV;   // global max of hard scores (scalar, as in ref)
    __syncthreads();

    float eG = __expf(-G);
    float sum = 0.f;
    for (int r = tid; r < BATCH; r += 256) {
        float nn = g_n[r];
        if (nn > 0.f) {
            float denom = __expf(-g_rm[r] * T_INV) * g_P[r] + eG * g_H[r];
            sum += logf(denom) - (g_S[r] * T_INV) / nn;
        }
    }
    sh[tid] = sum;
    __syncthreads();
    for (int s = 128; s; s >>= 1) {
        if (tid < s) sh[tid] += sh[tid + s];
        __syncthreads();
    }
    if (tid == 0) out[0] = sh[0] / (float)BATCH;
}

// ---------------------------------------------------------------------------
extern "C" void kernel_launch(void* const* d_in, const int* in_sizes, int n_in,
                              void* d_out, int out_size) {
    const float* x   = (const float*)d_in[0];
    const int*   idx = (const int*)d_in[1];   // raw words; dtype detected on device
    float*       out = (float*)d_out;

    const int smem_bytes = (DIM * PAD + BK * PAD + BM * PAD) * 4 + BN * 4;
    cudaFuncSetAttribute(sim_kernel, cudaFuncAttributeMaxDynamicSharedMemorySize,
                         smem_bytes);

    prep_idx_kernel<<<1, 256>>>(idx);
    normalize_kernel<<<BATCH, 128>>>(x);
    sim_kernel<<<BATCH / BM, 256, smem_bytes>>>();
    finalize_kernel<<<1, 256>>>(out);
}

// round 4
// speedup vs baseline: 5.9768x; 5.9768x over previous
#include <cuda_runtime.h>
#include <math_constants.h>
#include <cstdint>

#define BATCH 8192
#define DIM   512
#define T_INV 14.2857142857142857f  // 1/0.07

#define NSPLIT 16
#define TPC    4
#define MT     128
#define NT     128
#define KC     32
#define NCHUNK (DIM / KC)   // 16

#define PITCH  36           // floats per SMEM row (144B: 16B-aligned, conflict-free frags)
#define AB_FLOATS (MT * PITCH)          // 4608 floats per operand tile
#define STAGE_FLOATS (2 * AB_FLOATS)    // A + B
#define STAGE_BYTES  (STAGE_FLOATS * 4) // 36864
#define SMEM_BYTES   (2 * STAGE_BYTES)  // 73728 (C tile aliases over this)
#define CPITCH 132

// ---------------- static scratch ----------------
__device__ float g_f[BATCH * DIM];
__device__ int   g_idx[BATCH];
__device__ unsigned g_Gkey;
__device__ float g_pS[NSPLIT * BATCH], g_pP[NSPLIT * BATCH];
__device__ float g_pn[NSPLIT * BATCH], g_prm[NSPLIT * BATCH];
__device__ float g_pt[NSPLIT * BATCH * 5];
__device__ float g_D1[BATCH], g_H[BATCH], g_B[BATCH];

// ---------------- helpers ----------------
__device__ __forceinline__ uint32_t smem_u32(const void* p) {
    uint32_t a;
    asm("{ .reg .u64 t; cvta.to.shared.u64 t, %1; cvt.u32.u64 %0, t; }" : "=r"(a) : "l"(p));
    return a;
}
__device__ __forceinline__ float round_tf32(float x) {
    uint32_t u; asm("cvt.rna.tf32.f32 %0, %1;" : "=r"(u) : "f"(x));
    return __uint_as_float(u);
}
__device__ __forceinline__ void cpa16(uint32_t dst, const float* src) {
    asm volatile("cp.async.cg.shared.global [%0], [%1], 16;" :: "r"(dst), "l"(src));
}
#define CP_COMMIT() asm volatile("cp.async.commit_group;" ::: "memory")
#define CP_WAIT1()  asm volatile("cp.async.wait_group 1;" ::: "memory")
#define CP_WAIT0()  asm volatile("cp.async.wait_group 0;" ::: "memory")

__device__ __forceinline__ void mma8(float* c, const uint32_t* a, uint32_t b0, uint32_t b1) {
    asm volatile(
        "mma.sync.aligned.m16n8k8.row.col.f32.tf32.tf32.f32 "
        "{%0,%1,%2,%3}, {%4,%5,%6,%7}, {%8,%9}, {%0,%1,%2,%3};"
        : "+f"(c[0]), "+f"(c[1]), "+f"(c[2]), "+f"(c[3])
        : "r"(a[0]), "r"(a[1]), "r"(a[2]), "r"(a[3]), "r"(b0), "r"(b1));
}

__device__ __forceinline__ unsigned fkey(float f) {
    unsigned u = __float_as_uint(f);
    return (u & 0x80000000u) ? ~u : (u | 0x80000000u);
}
__device__ __forceinline__ float funkey(unsigned k) {
    unsigned u = (k & 0x80000000u) ? (k & 0x7FFFFFFFu) : ~k;
    return __uint_as_float(u);
}

// ---------------------------------------------------------------------------
// Kernel 0: dtype-agnostic index canonicalization (int32 vs int64) + G reset
// ---------------------------------------------------------------------------
__global__ void prep_idx_kernel(const int* __restrict__ raw) {
    __shared__ int sh[256];
    int tid = threadIdx.x;
    int acc = 0;
    for (int i = tid; i < BATCH / 2; i += 256) acc |= raw[2 * i + 1];
    sh[tid] = acc;
    __syncthreads();
    for (int s = 128; s; s >>= 1) { if (tid < s) sh[tid] |= sh[tid + s]; __syncthreads(); }
    bool is64 = (sh[0] == 0);
    for (int i = tid; i < BATCH; i += 256) g_idx[i] = is64 ? raw[2 * i] : raw[i];
    if (tid == 0) g_Gkey = 0u;
}

// ---------------------------------------------------------------------------
// Kernel 1: L2 normalize + pre-round to tf32 (rna)
// ---------------------------------------------------------------------------
__global__ void normalize_kernel(const float* __restrict__ x) {
    int row = blockIdx.x;
    int t = threadIdx.x;
    const float4* xr = (const float4*)(x + row * DIM);
    float4 v = xr[t];
    float ss = v.x * v.x + v.y * v.y + v.z * v.z + v.w * v.w;
    #pragma unroll
    for (int o = 16; o; o >>= 1) ss += __shfl_xor_sync(0xffffffffu, ss, o);
    __shared__ float ws[4];
    if ((t & 31) == 0) ws[t >> 5] = ss;
    __syncthreads();
    float inv = 1.0f / fmaxf(sqrtf(ws[0] + ws[1] + ws[2] + ws[3]), 1e-12f);
    v.x = round_tf32(v.x * inv); v.y = round_tf32(v.y * inv);
    v.z = round_tf32(v.z * inv); v.w = round_tf32(v.w * inv);
    ((float4*)(g_f + row * DIM))[t] = v;
}

// ---------------------------------------------------------------------------
// Kernel 2: HMMA tf32 sim GEMM (cp.async 2-stage) + fused per-row scan
//   grid = 64 strips x 16 splits; block = 256 (8 warps, 4x2 of 32x64 tiles)
// ---------------------------------------------------------------------------
__device__ __forceinline__ void prefetch_chunk(uint32_t s_base, int st, int row0,
                                               int col0, int kb, int tid) {
    const uint32_t stf = s_base + st * STAGE_BYTES;
    #pragma unroll
    for (int i = tid; i < MT * 8; i += 256) {       // A: 128 rows x 8 segs of 16B
        int r = i >> 3, sg = i & 7;
        cpa16(stf + (r * PITCH + sg * 4) * 4, g_f + (row0 + r) * DIM + kb + sg * 4);
    }
    #pragma unroll
    for (int i = tid; i < NT * 8; i += 256) {       // B
        int r = i >> 3, sg = i & 7;
        cpa16(stf + AB_FLOATS * 4 + (r * PITCH + sg * 4) * 4,
              g_f + (col0 + r) * DIM + kb + sg * 4);
    }
    CP_COMMIT();
}

__global__ __launch_bounds__(256, 2)
void sim_kernel() {
    extern __shared__ float smem[];
    const uint32_t s_base = smem_u32(smem);
    const int tid  = threadIdx.x;
    const int lane = tid & 31, warp = tid >> 5;
    const int strip = blockIdx.x >> 4;
    const int split = blockIdx.x & (NSPLIT - 1);
    const int row0 = strip * MT;
    const int wm = warp >> 1, wn = warp & 1;   // 4x2 warp grid
    const int qg = lane >> 2, qt = lane & 3;

    // scan state (threads 0..127)
    float S = 0.f, P = 0.f, n = 0.f, rm = -CUDART_INF_F;
    float t0 = -CUDART_INF_F, t1 = -CUDART_INF_F, t2 = -CUDART_INF_F,
          t3 = -CUDART_INF_F, t4 = -CUDART_INF_F;
    const int myrow = row0 + (tid & 127);
    const int myidx = g_idx[myrow];

    for (int tile = 0; tile < TPC; tile++) {
        const int col0 = split * (TPC * NT) + tile * NT;
        float acc[2][8][4];
        #pragma unroll
        for (int i = 0; i < 2; i++)
            #pragma unroll
            for (int j = 0; j < 8; j++)
                #pragma unroll
                for (int q = 0; q < 4; q++) acc[i][j][q] = 0.f;

        prefetch_chunk(s_base, 0, row0, col0, 0, tid);
        prefetch_chunk(s_base, 1, row0, col0, KC, tid);

        for (int c = 0; c < NCHUNK; c++) {
            const int st = c & 1;
            if (c >= NCHUNK - 2) { CP_WAIT0(); } else { CP_WAIT1(); }
            __syncthreads();
            const float* As = smem + st * STAGE_FLOATS;
            const float* Bs = As + AB_FLOATS;
            const float* apb = As + (wm * 32) * PITCH + qt;
            const float* bpb = Bs + (wn * 64 + qg) * PITCH + qt;
            #pragma unroll
            for (int ks = 0; ks < 4; ks++) {
                const int kk = ks * 8;
                uint32_t a[2][4];
                #pragma unroll
                for (int i = 0; i < 2; i++) {
                    const float* ap = apb + i * 16 * PITCH + kk;
                    a[i][0] = __float_as_uint(ap[qg * PITCH]);
                    a[i][1] = __float_as_uint(ap[(qg + 8) * PITCH]);
                    a[i][2] = __float_as_uint(ap[qg * PITCH + 4]);
                    a[i][3] = __float_as_uint(ap[(qg + 8) * PITCH + 4]);
                }
                #pragma unroll
                for (int j = 0; j < 8; j++) {
                    const float* bp = bpb + j * 8 * PITCH + kk;
                    uint32_t b0 = __float_as_uint(bp[0]);
                    uint32_t b1 = __float_as_uint(bp[4]);
                    mma8(acc[0][j], a[0], b0, b1);
                    mma8(acc[1][j], a[1], b0, b1);
                }
            }
            __syncthreads();
            if (c + 2 < NCHUNK)
                prefetch_chunk(s_base, st, row0, col0, (c + 2) * KC, tid);
        }

        // stage C tile (alias over stage buffers; all mma reads done)
        float* Cs = smem;
        #pragma unroll
        for (int i = 0; i < 2; i++) {
            #pragma unroll
            for (int j = 0; j < 8; j++) {
                int r = wm * 32 + i * 16 + qg;
                int cc = wn * 64 + j * 8 + 2 * qt;
                Cs[r * CPITCH + cc]           = acc[i][j][0];
                Cs[r * CPITCH + cc + 1]       = acc[i][j][1];
                Cs[(r + 8) * CPITCH + cc]     = acc[i][j][2];
                Cs[(r + 8) * CPITCH + cc + 1] = acc[i][j][3];
            }
        }
        __syncthreads();

        if (tid < 128) {
            const float* crow = Cs + tid * CPITCH;
            for (int cc = 0; cc < NT; cc++) {
                int gcol = col0 + cc;
                if (gcol == myrow) continue;
                float v = crow[cc];
                if (v > t4) {
                    float w = v, tmp;
                    if (w > t0) { tmp = t0; t0 = w; w = tmp; }
                    if (w > t1) { tmp = t1; t1 = w; w = tmp; }
                    if (w > t2) { tmp = t2; t2 = w; w = tmp; }
                    if (w > t3) { tmp = t3; t3 = w; w = tmp; }
                    t4 = w;
                }
                if (__ldg(&g_idx[gcol]) == myidx) {
                    n += 1.0f; S += v; rm = fmaxf(rm, v);
                    P += __expf(v * T_INV);
                }
            }
        }
        __syncthreads();   // scan done before next tile's prefetch overwrites
    }

    if (tid < 128) {
        int base = split * BATCH + myrow;
        g_pS[base] = S; g_pP[base] = P; g_pn[base] = n; g_prm[base] = rm;
        float* tp = g_pt + (size_t)base * 5;
        tp[0] = t0; tp[1] = t1; tp[2] = t2; tp[3] = t3; tp[4] = t4;
    }
}

// ---------------------------------------------------------------------------
// Kernel 3: merge partials; compute per-row terms; deterministic global max
// ---------------------------------------------------------------------------
__global__ void merge_kernel() {
    int r = blockIdx.x * 256 + threadIdx.x;
    float S = 0.f, P = 0.f, n = 0.f, rm = -CUDART_INF_F;
    float t0 = -CUDART_INF_F, t1 = -CUDART_INF_F, t2 = -CUDART_INF_F,
          t3 = -CUDART_INF_F, t4 = -CUDART_INF_F;
    #pragma unroll
    for (int s = 0; s < NSPLIT; s++) {
        int b = s * BATCH + r;
        S += g_pS[b]; P += g_pP[b]; n += g_pn[b]; rm = fmaxf(rm, g_prm[b]);
        const float* tp = g_pt + (size_t)b * 5;
        #pragma unroll
        for (int j = 0; j < 5; j++) {
            float v = tp[j];
            if (v > t4) {
                float w = v, tmp;
                if (w > t0) { tmp = t0; t0 = w; w = tmp; }
                if (w > t1) { tmp = t1; t1 = w; w = tmp; }
                if (w > t2) { tmp = t2; t2 = w; w = tmp; }
                if (w > t3) { tmp = t3; t3 = w; w = tmp; }
                t4 = w;
            }
        }
    }
    g_D1[r] = (n > 0.f) ? __expf(-rm * T_INV) * P : 0.f;
    g_H[r]  = __expf(t0 * T_INV) + __expf(t1 * T_INV) + __expf(t2 * T_INV) +
              __expf(t3 * T_INV) + __expf(t4 * T_INV);
    g_B[r]  = (n > 0.f) ? (S * T_INV) / n : 0.f;
    if (n <= 0.f) g_H[r] = -1.f;   // sentinel: row contributes 0

    __shared__ unsigned sm[256];
    sm[threadIdx.x] = fkey(t0);
    __syncthreads();
    for (int s = 128; s; s >>= 1) {
        if (threadIdx.x < s) sm[threadIdx.x] = max(sm[threadIdx.x], sm[threadIdx.x + s]);
        __syncthreads();
    }
    if (threadIdx.x == 0) atomicMax(&g_Gkey, sm[0]);
}

// ---------------------------------------------------------------------------
// Kernel 4: final loss
// ---------------------------------------------------------------------------
__global__ void finalize_kernel(float* __restrict__ out) {
    __shared__ float sh[1024];
    int tid = threadIdx.x;
    float G = funkey(g_Gkey) * T_INV;
    float eG = __expf(-G);
    float sum = 0.f;
    for (int r = tid; r < BATCH; r += 1024) {
        float H = g_H[r];
        if (H >= 0.f)
            sum += __logf(g_D1[r] + eG * H) - g_B[r];
    }
    sh[tid] = sum;
    __syncthreads();
    for (int s = 512; s; s >>= 1) {
        if (tid < s) sh[tid] += sh[tid + s];
        __syncthreads();
    }
    if (tid == 0) out[0] = sh[0] / (float)BATCH;
}

// ---------------------------------------------------------------------------
extern "C" void kernel_launch(void* const* d_in, const int* in_sizes, int n_in,
                              void* d_out, int out_size) {
    const float* x   = (const float*)d_in[0];
    const int*   idx = (const int*)d_in[1];
    float*       out = (float*)d_out;

    cudaFuncSetAttribute(sim_kernel, cudaFuncAttributeMaxDynamicSharedMemorySize,
                         SMEM_BYTES);

    prep_idx_kernel<<<1, 256>>>(idx);
    normalize_kernel<<<BATCH, 128>>>(x);
    sim_kernel<<<64 * NSPLIT, 256, SMEM_BYTES>>>();
    merge_kernel<<<BATCH / 256, 256>>>();
    finalize_kernel<<<1, 1024>>>(out);
}

// round 5
// speedup vs baseline: 10.1564x; 1.6993x over previous
#include <cuda_runtime.h>
#include <cuda_bf16.h>
#include <math_constants.h>
#include <cstdint>

#define BATCH 8192
#define DIM   512
#define T_INV 14.2857142857142857f  // 1/0.07

#define NSPLIT 16
#define TPC    4
#define MT     128
#define NT     128
#define KC     64                  // bf16 halves per chunk
#define NCHUNK (DIM / KC)          // 8

#define PITCHH 72                  // halves per SMEM row (144B; conflict-free frags)
#define PITCH32 (PITCHH / 2)       // 36 uint32 per row
#define AB_HALVES (MT * PITCHH)            // 9216 halves = 18432 B per operand
#define STAGE_HALVES (2 * AB_HALVES)
#define STAGE_BYTES  (STAGE_HALVES * 2)    // 36864
#define SMEM_BYTES   (2 * STAGE_BYTES)     // 73728 (C tile + partials alias)
#define CPITCH 132

// ---------------- static scratch ----------------
__device__ __nv_bfloat16 g_fb[BATCH * DIM];
__device__ int   g_idx[BATCH];
__device__ unsigned g_Gkey;
__device__ float g_pS[NSPLIT * BATCH], g_pP[NSPLIT * BATCH];
__device__ float g_pn[NSPLIT * BATCH], g_prm[NSPLIT * BATCH];
__device__ float g_pt[NSPLIT * BATCH * 5];
__device__ float g_D1[BATCH], g_H[BATCH], g_B[BATCH];

// ---------------- helpers ----------------
__device__ __forceinline__ uint32_t smem_u32(const void* p) {
    uint32_t a;
    asm("{ .reg .u64 t; cvta.to.shared.u64 t, %1; cvt.u32.u64 %0, t; }" : "=r"(a) : "l"(p));
    return a;
}
__device__ __forceinline__ void cpa16(uint32_t dst, const void* src) {
    asm volatile("cp.async.cg.shared.global [%0], [%1], 16;" :: "r"(dst), "l"(src));
}
#define CP_COMMIT() asm volatile("cp.async.commit_group;" ::: "memory")
#define CP_WAIT1()  asm volatile("cp.async.wait_group 1;" ::: "memory")
#define CP_WAIT0()  asm volatile("cp.async.wait_group 0;" ::: "memory")

__device__ __forceinline__ void mma16(float* c, const uint32_t* a, uint32_t b0, uint32_t b1) {
    asm volatile(
        "mma.sync.aligned.m16n8k16.row.col.f32.bf16.bf16.f32 "
        "{%0,%1,%2,%3}, {%4,%5,%6,%7}, {%8,%9}, {%0,%1,%2,%3};"
        : "+f"(c[0]), "+f"(c[1]), "+f"(c[2]), "+f"(c[3])
        : "r"(a[0]), "r"(a[1]), "r"(a[2]), "r"(a[3]), "r"(b0), "r"(b1));
}

__device__ __forceinline__ unsigned fkey(float f) {
    unsigned u = __float_as_uint(f);
    return (u & 0x80000000u) ? ~u : (u | 0x80000000u);
}
__device__ __forceinline__ float funkey(unsigned k) {
    unsigned u = (k & 0x80000000u) ? (k & 0x7FFFFFFFu) : ~k;
    return __uint_as_float(u);
}
__device__ __forceinline__ void top5_ins(float v, float& t0, float& t1, float& t2,
                                         float& t3, float& t4) {
    if (v > t4) {
        float w = v, tmp;
        if (w > t0) { tmp = t0; t0 = w; w = tmp; }
        if (w > t1) { tmp = t1; t1 = w; w = tmp; }
        if (w > t2) { tmp = t2; t2 = w; w = tmp; }
        if (w > t3) { tmp = t3; t3 = w; w = tmp; }
        t4 = w;
    }
}

// ---------------------------------------------------------------------------
// Kernel 0: dtype-agnostic index canonicalization (int32 vs int64) + G reset
// ---------------------------------------------------------------------------
__global__ void prep_idx_kernel(const int* __restrict__ raw) {
    __shared__ int sh[256];
    int tid = threadIdx.x;
    int acc = 0;
    for (int i = tid; i < BATCH / 2; i += 256) acc |= raw[2 * i + 1];
    sh[tid] = acc;
    __syncthreads();
    for (int s = 128; s; s >>= 1) { if (tid < s) sh[tid] |= sh[tid + s]; __syncthreads(); }
    bool is64 = (sh[0] == 0);
    for (int i = tid; i < BATCH; i += 256) g_idx[i] = is64 ? raw[2 * i] : raw[i];
    if (tid == 0) g_Gkey = 0u;
}

// ---------------------------------------------------------------------------
// Kernel 1: L2 normalize + round to bf16 (rn)
// ---------------------------------------------------------------------------
__global__ void normalize_kernel(const float* __restrict__ x) {
    int row = blockIdx.x;
    int t = threadIdx.x;
    float4 v = ((const float4*)(x + row * DIM))[t];
    float ss = v.x * v.x + v.y * v.y + v.z * v.z + v.w * v.w;
    #pragma unroll
    for (int o = 16; o; o >>= 1) ss += __shfl_xor_sync(0xffffffffu, ss, o);
    __shared__ float ws[4];
    if ((t & 31) == 0) ws[t >> 5] = ss;
    __syncthreads();
    float inv = 1.0f / fmaxf(sqrtf(ws[0] + ws[1] + ws[2] + ws[3]), 1e-12f);
    __nv_bfloat162 p0 = __floats2bfloat162_rn(v.x * inv, v.y * inv);
    __nv_bfloat162 p1 = __floats2bfloat162_rn(v.z * inv, v.w * inv);
    uint2 w;
    w.x = *(uint32_t*)&p0;
    w.y = *(uint32_t*)&p1;
    ((uint2*)(g_fb + row * DIM))[t] = w;
}

// ---------------------------------------------------------------------------
// Kernel 2: HMMA bf16 sim GEMM (cp.async 2-stage) + fused per-row scan
//   grid = 64 strips x 16 splits; block = 256 (8 warps, 4x2 of 32x64 tiles)
// ---------------------------------------------------------------------------
__device__ __forceinline__ void prefetch_chunk(uint32_t s_base, int st, int row0,
                                               int col0, int kb, int tid) {
    const uint32_t stf = s_base + st * STAGE_BYTES;
    #pragma unroll
    for (int i = tid; i < MT * 8; i += 256) {       // A: 128 rows x 8 segs of 16B
        int r = i >> 3, sg = i & 7;
        cpa16(stf + (r * PITCHH + sg * 8) * 2, g_fb + (row0 + r) * DIM + kb + sg * 8);
    }
    #pragma unroll
    for (int i = tid; i < NT * 8; i += 256) {       // B
        int r = i >> 3, sg = i & 7;
        cpa16(stf + AB_HALVES * 2 + (r * PITCHH + sg * 8) * 2,
              g_fb + (col0 + r) * DIM + kb + sg * 8);
    }
    CP_COMMIT();
}

__global__ __launch_bounds__(256, 2)
void sim_kernel() {
    extern __shared__ float smem[];
    const uint32_t s_base = smem_u32(smem);
    const int tid  = threadIdx.x;
    const int lane = tid & 31, warp = tid >> 5;
    const int strip = blockIdx.x >> 4;
    const int split = blockIdx.x & (NSPLIT - 1);
    const int row0 = strip * MT;
    const int wm = warp >> 1, wn = warp & 1;
    const int qg = lane >> 2, qt = lane & 3;

    // persistent per-row scan state (threads 0..127 own row = row0 + tid)
    float S = 0.f, P = 0.f, n = 0.f, rm = -CUDART_INF_F;
    float t0 = -CUDART_INF_F, t1 = -CUDART_INF_F, t2 = -CUDART_INF_F,
          t3 = -CUDART_INF_F, t4 = -CUDART_INF_F;
    const int srow = tid & 127, shalf = tid >> 7;
    const int myrow = row0 + srow;
    const int myidx = g_idx[myrow];

    for (int tile = 0; tile < TPC; tile++) {
        const int col0 = split * (TPC * NT) + tile * NT;
        float acc[2][8][4];
        #pragma unroll
        for (int i = 0; i < 2; i++)
            #pragma unroll
            for (int j = 0; j < 8; j++)
                #pragma unroll
                for (int q = 0; q < 4; q++) acc[i][j][q] = 0.f;

        prefetch_chunk(s_base, 0, row0, col0, 0, tid);
        prefetch_chunk(s_base, 1, row0, col0, KC, tid);

        for (int c = 0; c < NCHUNK; c++) {
            const int st = c & 1;
            if (c >= NCHUNK - 2) { CP_WAIT0(); } else { CP_WAIT1(); }
            __syncthreads();
            const uint32_t* As = (const uint32_t*)smem + st * (STAGE_HALVES / 2);
            const uint32_t* Bs = As + AB_HALVES / 2;
            const uint32_t* apb = As + (wm * 32 + qg) * PITCH32 + qt;
            const uint32_t* bpb = Bs + (wn * 64 + qg) * PITCH32 + qt;
            #pragma unroll
            for (int ks = 0; ks < 4; ks++) {
                const int kk2 = ks * 8;   // u32 offset of this k16 step
                uint32_t a[2][4];
                #pragma unroll
                for (int i = 0; i < 2; i++) {
                    const uint32_t* ap = apb + i * 16 * PITCH32 + kk2;
                    a[i][0] = ap[0];
                    a[i][1] = ap[8 * PITCH32];
                    a[i][2] = ap[4];
                    a[i][3] = ap[8 * PITCH32 + 4];
                }
                #pragma unroll
                for (int j = 0; j < 8; j++) {
                    const uint32_t* bp = bpb + j * 8 * PITCH32 + kk2;
                    uint32_t b0 = bp[0];
                    uint32_t b1 = bp[4];
                    mma16(acc[0][j], a[0], b0, b1);
                    mma16(acc[1][j], a[1], b0, b1);
                }
            }
            __syncthreads();
            if (c + 2 < NCHUNK)
                prefetch_chunk(s_base, st, row0, col0, (c + 2) * KC, tid);
        }

        // stage C tile (aliases stage buffers; all mma reads complete)
        float* Cs = smem;
        float* Ps = smem + 128 * CPITCH;    // 128 rows x 9 partial floats
        #pragma unroll
        for (int i = 0; i < 2; i++) {
            #pragma unroll
            for (int j = 0; j < 8; j++) {
                int r = wm * 32 + i * 16 + qg;
                int cc = wn * 64 + j * 8 + 2 * qt;
                Cs[r * CPITCH + cc]           = acc[i][j][0];
                Cs[r * CPITCH + cc + 1]       = acc[i][j][1];
                Cs[(r + 8) * CPITCH + cc]     = acc[i][j][2];
                Cs[(r + 8) * CPITCH + cc + 1] = acc[i][j][3];
            }
        }
        __syncthreads();

        // split scan: each row handled by 2 threads (64 cols each)
        {
            const float* crow = Cs + srow * CPITCH + shalf * 64;
            const int colbase = col0 + shalf * 64;
            float lS = 0.f, lP = 0.f, ln = 0.f, lrm = -CUDART_INF_F;
            float l0 = -CUDART_INF_F, l1 = -CUDART_INF_F, l2 = -CUDART_INF_F,
                  l3 = -CUDART_INF_F, l4 = -CUDART_INF_F;
            for (int cc = 0; cc < 64; cc++) {
                int gcol = colbase + cc;
                if (gcol == myrow) continue;
                float v = crow[cc];
                top5_ins(v, l0, l1, l2, l3, l4);
                if (__ldg(&g_idx[gcol]) == myidx) {
                    ln += 1.0f; lS += v; lrm = fmaxf(lrm, v);
                    lP += __expf(v * T_INV);
                }
            }
            if (shalf) {
                float* pp = Ps + srow * 9;
                pp[0] = lS; pp[1] = lP; pp[2] = ln; pp[3] = lrm;
                pp[4] = l0; pp[5] = l1; pp[6] = l2; pp[7] = l3; pp[8] = l4;
            } else {
                // fold local half into persistent state
                S += lS; P += lP; n += ln; rm = fmaxf(rm, lrm);
                top5_ins(l0, t0, t1, t2, t3, t4);
                top5_ins(l1, t0, t1, t2, t3, t4);
                top5_ins(l2, t0, t1, t2, t3, t4);
                top5_ins(l3, t0, t1, t2, t3, t4);
                top5_ins(l4, t0, t1, t2, t3, t4);
            }
            __syncthreads();
            if (!shalf) {
                const float* pp = Ps + srow * 9;
                S += pp[0]; P += pp[1]; n += pp[2]; rm = fmaxf(rm, pp[3]);
                top5_ins(pp[4], t0, t1, t2, t3, t4);
                top5_ins(pp[5], t0, t1, t2, t3, t4);
                top5_ins(pp[6], t0, t1, t2, t3, t4);
                top5_ins(pp[7], t0, t1, t2, t3, t4);
                top5_ins(pp[8], t0, t1, t2, t3, t4);
            }
        }
        __syncthreads();   // scans done before next tile's prefetch overwrites
    }

    if (tid < 128) {
        int base = split * BATCH + myrow;
        g_pS[base] = S; g_pP[base] = P; g_pn[base] = n; g_prm[base] = rm;
        float* tp = g_pt + (size_t)base * 5;
        tp[0] = t0; tp[1] = t1; tp[2] = t2; tp[3] = t3; tp[4] = t4;
    }
}

// ---------------------------------------------------------------------------
// Kernel 3: merge partials; compute per-row terms; deterministic global max
// ---------------------------------------------------------------------------
__global__ void merge_kernel() {
    int r = blockIdx.x * 256 + threadIdx.x;
    float S = 0.f, P = 0.f, n = 0.f, rm = -CUDART_INF_F;
    float t0 = -CUDART_INF_F, t1 = -CUDART_INF_F, t2 = -CUDART_INF_F,
          t3 = -CUDART_INF_F, t4 = -CUDART_INF_F;
    #pragma unroll
    for (int s = 0; s < NSPLIT; s++) {
        int b = s * BATCH + r;
        S += g_pS[b]; P += g_pP[b]; n += g_pn[b]; rm = fmaxf(rm, g_prm[b]);
        const float* tp = g_pt + (size_t)b * 5;
        #pragma unroll
        for (int j = 0; j < 5; j++) top5_ins(tp[j], t0, t1, t2, t3, t4);
    }
    g_D1[r] = (n > 0.f) ? __expf(-rm * T_INV) * P : 0.f;
    g_H[r]  = __expf(t0 * T_INV) + __expf(t1 * T_INV) + __expf(t2 * T_INV) +
              __expf(t3 * T_INV) + __expf(t4 * T_INV);
    g_B[r]  = (n > 0.f) ? (S * T_INV) / n : 0.f;
    if (n <= 0.f) g_H[r] = -1.f;   // sentinel: row contributes 0

    __shared__ unsigned sm[256];
    sm[threadIdx.x] = fkey(t0);
    __syncthreads();
    for (int s = 128; s; s >>= 1) {
        if (threadIdx.x < s) sm[threadIdx.x] = max(sm[threadIdx.x], sm[threadIdx.x + s]);
        __syncthreads();
    }
    if (threadIdx.x == 0) atomicMax(&g_Gkey, sm[0]);
}

// ---------------------------------------------------------------------------
// Kernel 4: final loss
// ---------------------------------------------------------------------------
__global__ void finalize_kernel(float* __restrict__ out) {
    __shared__ float sh[1024];
    int tid = threadIdx.x;
    float G = funkey(g_Gkey) * T_INV;
    float eG = __expf(-G);
    float sum = 0.f;
    for (int r = tid; r < BATCH; r += 1024) {
        float H = g_H[r];
        if (H >= 0.f)
            sum += __logf(g_D1[r] + eG * H) - g_B[r];
    }
    sh[tid] = sum;
    __syncthreads();
    for (int s = 512; s; s >>= 1) {
        if (tid < s) sh[tid] += sh[tid + s];
        __syncthreads();
    }
    if (tid == 0) out[0] = sh[0] / (float)BATCH;
}

// ---------------------------------------------------------------------------
extern "C" void kernel_launch(void* const* d_in, const int* in_sizes, int n_in,
                              void* d_out, int out_size) {
    const float* x   = (const float*)d_in[0];
    const int*   idx = (const int*)d_in[1];
    float*       out = (float*)d_out;

    cudaFuncSetAttribute(sim_kernel, cudaFuncAttributeMaxDynamicSharedMemorySize,
                         SMEM_BYTES);

    prep_idx_kernel<<<1, 256>>>(idx);
    normalize_kernel<<<BATCH, 128>>>(x);
    sim_kernel<<<64 * NSPLIT, 256, SMEM_BYTES>>>();
    merge_kernel<<<BATCH / 256, 256>>>();
    finalize_kernel<<<1, 1024>>>(out);
}